// round 13
// baseline (speedup 1.0000x reference)
#include <cuda_runtime.h>
#include <cuda_bf16.h>
#include <cstdint>

// Problem constants
#define Bn   32
#define Tn   256
#define Un   128
#define Um1  127
#define Vn   4096
#define ND   383            // number of anti-diagonals (Tn+Un-1)

// ---------------- device scratch ---------------------------------------------
__device__ __align__(16) float gd_blank[(size_t)Bn * ND * 128]; // diag-major blank_lp
__device__ __align__(16) float gd_lab  [(size_t)Bn * ND * 128]; // diag-major lab_lp

// ---------------- PTX helpers ------------------------------------------------
__device__ __forceinline__ uint32_t smem_u32(const void* p) {
    uint32_t a;
    asm("{ .reg .u64 t; cvta.to.shared.u64 t, %1; cvt.u32.u64 %0, t; }"
        : "=r"(a) : "l"(p));
    return a;
}
#define LDSM4(r0, r1, r2, r3, addr) \
    asm volatile("ldmatrix.sync.aligned.m8n8.x4.shared.b16 {%0,%1,%2,%3}, [%4];" \
        : "=r"(r0), "=r"(r1), "=r"(r2), "=r"(r3) : "r"(addr))

#define MMA16816(c, a, bq) \
    asm volatile("mma.sync.aligned.m16n8k16.row.col.f32.bf16.bf16.f32 " \
        "{%0,%1,%2,%3}, {%4,%5,%6,%7}, {%8,%9}, {%0,%1,%2,%3};" \
        : "+f"((c)[0]), "+f"((c)[1]), "+f"((c)[2]), "+f"((c)[3]) \
        : "r"((a)[0]), "r"((a)[1]), "r"((a)[2]), "r"((a)[3]), \
          "r"((bq)[0]), "r"((bq)[1]))

// exp + pack 8 floats -> 8 bf16 (one 16B uint4)
__device__ __forceinline__ uint4 exp_cvt8(float4 v0, float4 v1) {
    __nv_bfloat162 o0 = __floats2bfloat162_rn(__expf(v0.x), __expf(v0.y));
    __nv_bfloat162 o1 = __floats2bfloat162_rn(__expf(v0.z), __expf(v0.w));
    __nv_bfloat162 o2 = __floats2bfloat162_rn(__expf(v1.x), __expf(v1.y));
    __nv_bfloat162 o3 = __floats2bfloat162_rn(__expf(v1.z), __expf(v1.w));
    uint4 pk;
    pk.x = *(uint32_t*)&o0;
    pk.y = *(uint32_t*)&o1;
    pk.z = *(uint32_t*)&o2;
    pk.w = *(uint32_t*)&o3;
    return pk;
}

// ---------------- kernel 1: fused exp -> bf16 -> HMMA GEMM -------------------
// CTA tile: 64(t) x 128(u); K = 4096 in 64 chunks of BK=64 (128B bf16 rows).
// 8 warps as 2(m) x 4(n); warp tile 32x32 via mma.m16n8k16.
// Producer: LDG f32 -> __expf -> bf16 -> STS, 2-chunk register prefetch,
// 2-stage smem double buffer. (exp overflow impossible: randn inputs.)
#define SMEM_HDR  2048
#define STAGE_B   24576            // A 64x128B + B 128x128B
#define SMEM_TOT  (SMEM_HDR + 2 * STAGE_B)   // 51200

__global__ __launch_bounds__(256, 1) void gemm_kernel(const float* __restrict__ E,
                                                      const float* __restrict__ P,
                                                      const int* __restrict__ labels) {
    extern __shared__ __align__(1024) char smem[];
    uint32_t sb = smem_u32(smem);
    float* p0s = (float*)(smem);
    float* pls = (float*)(smem + 512);
    int*   lbs = (int*)(smem + 1024);

    int tid = threadIdx.x, lane = tid & 31, wid = tid >> 5;
    int wm = wid >> 2;              // 0..1  (m group of 32 rows)
    int wn = wid & 3;               // 0..3  (n group of 32 cols)
    int t0 = blockIdx.x * 64;
    int b  = blockIdx.y;

    // header: p0, p_lab, labels for this batch
    if (tid < Un) {
        const float* Pr = P + (size_t)(b * Un + tid) * Vn;
        p0s[tid] = Pr[0];
        if (tid < Um1) {
            int l = labels[b * Um1 + tid];
            lbs[tid] = l;
            pls[tid] = Pr[l];
        }
    }

    // producer mapping:
    //   A: row ra = tid>>2 (64 rows), 16 k-cols from ca = (tid&3)*16
    //   B: row rb = tid>>1 (128 rows), 32 k-cols from cb = (tid&1)*32
    const int ra = tid >> 2;
    const int rb = tid >> 1;
    const float4* Abase = (const float4*)(E + (size_t)(b * Tn + t0 + ra) * Vn
                                            + (tid & 3) * 16);
    const float4* Bbase = (const float4*)(P + (size_t)(b * Un + rb) * Vn
                                            + (tid & 1) * 32);
    // precomputed swizzled smem byte offsets (stage-relative)
    uint32_t aoff[2], boff[4];
    {
        int ccA = (tid & 3) * 2;
        aoff[0] = (uint32_t)(ra * 128 + (((ccA + 0) ^ (ra & 7)) << 4));
        aoff[1] = (uint32_t)(ra * 128 + (((ccA + 1) ^ (ra & 7)) << 4));
        int ccB = (tid & 1) * 4;
        boff[0] = (uint32_t)(8192 + rb * 128 + (((ccB + 0) ^ (rb & 7)) << 4));
        boff[1] = (uint32_t)(8192 + rb * 128 + (((ccB + 1) ^ (rb & 7)) << 4));
        boff[2] = (uint32_t)(8192 + rb * 128 + (((ccB + 2) ^ (rb & 7)) << 4));
        boff[3] = (uint32_t)(8192 + rb * 128 + (((ccB + 3) ^ (rb & 7)) << 4));
    }

    float4 rA0, rA1, rA2, rA3;
    float4 rB0, rB1, rB2, rB3, rB4, rB5, rB6, rB7;

#define LOAD_REGS(kk) do { int koff = (kk) * 16; \
        rA0 = Abase[koff + 0]; rA1 = Abase[koff + 1]; \
        rA2 = Abase[koff + 2]; rA3 = Abase[koff + 3]; \
        rB0 = Bbase[koff + 0]; rB1 = Bbase[koff + 1]; \
        rB2 = Bbase[koff + 2]; rB3 = Bbase[koff + 3]; \
        rB4 = Bbase[koff + 4]; rB5 = Bbase[koff + 5]; \
        rB6 = Bbase[koff + 6]; rB7 = Bbase[koff + 7]; } while (0)

#define CVT_STS(ss) do { char* stg = smem + SMEM_HDR + (ss) * STAGE_B; \
        *(uint4*)(stg + aoff[0]) = exp_cvt8(rA0, rA1); \
        *(uint4*)(stg + aoff[1]) = exp_cvt8(rA2, rA3); \
        *(uint4*)(stg + boff[0]) = exp_cvt8(rB0, rB1); \
        *(uint4*)(stg + boff[1]) = exp_cvt8(rB2, rB3); \
        *(uint4*)(stg + boff[2]) = exp_cvt8(rB4, rB5); \
        *(uint4*)(stg + boff[3]) = exp_cvt8(rB6, rB7); } while (0)

    LOAD_REGS(0);
    CVT_STS(0);
    LOAD_REGS(1);
    __syncthreads();

    float cr[2][4][4] = {};

    for (int k = 0; k < 64; k++) {
        uint32_t sA = sb + SMEM_HDR + (k & 1) * STAGE_B;
        uint32_t sB = sA + 8192;
#pragma unroll
        for (int kf = 0; kf < 4; kf++) {
            uint32_t afr[2][4], bfr[4][2];
#pragma unroll
            for (int mi = 0; mi < 2; mi++) {
                int row = wm * 32 + mi * 16 + (lane & 15);
                int kc  = kf * 2 + (lane >> 4);
                uint32_t ad = sA + row * 128 + (((uint32_t)(kc ^ (row & 7))) << 4);
                LDSM4(afr[mi][0], afr[mi][1], afr[mi][2], afr[mi][3], ad);
            }
#pragma unroll
            for (int p = 0; p < 2; p++) {
                int g = lane >> 3;
                int nrow = wn * 32 + p * 16 + ((g >> 1) << 3) + (lane & 7);
                int kc   = kf * 2 + (g & 1);
                uint32_t bd = sB + nrow * 128 + (((uint32_t)(kc ^ (nrow & 7))) << 4);
                uint32_t r0, r1, r2, r3;
                LDSM4(r0, r1, r2, r3, bd);
                bfr[p * 2 + 0][0] = r0; bfr[p * 2 + 0][1] = r1;
                bfr[p * 2 + 1][0] = r2; bfr[p * 2 + 1][1] = r3;
            }
#pragma unroll
            for (int mi = 0; mi < 2; mi++)
#pragma unroll
                for (int ni = 0; ni < 4; ni++)
                    MMA16816(cr[mi][ni], afr[mi], bfr[ni]);
        }
        __syncthreads();                 // all readers of stage k&1 done
        if (k + 1 < 64) CVT_STS((k + 1) & 1);
        if (k + 2 < 64) LOAD_REGS(k + 2);
        __syncthreads();                 // stage (k+1)&1 writes visible
    }

    // ---- epilogue: direct diag-major scattered writes (best variant) --------
    float* gbd = gd_blank + (size_t)b * ND * 128;
    float* gld = gd_lab   + (size_t)b * ND * 128;
#pragma unroll
    for (int mi = 0; mi < 2; mi++) {
#pragma unroll
        for (int h = 0; h < 2; h++) {
            int t = t0 + wm * 32 + mi * 16 + h * 8 + (lane >> 2);
            const float* Er = E + (size_t)(b * Tn + t) * Vn;
            float e0 = Er[0];
#pragma unroll
            for (int ni = 0; ni < 4; ni++) {
#pragma unroll
                for (int j = 0; j < 2; j++) {
                    int u = wn * 32 + ni * 8 + (lane & 3) * 2 + j;
                    float ln = __logf(cr[mi][ni][h * 2 + j]);
                    gbd[(t + u) * 128 + u] = e0 + p0s[u] - ln;
                    if (u < Um1)
                        gld[(t + u) * 128 + u] = Er[lbs[u]] + pls[u] - ln;
                }
            }
        }
    }
}

// ---------------- kernel 2: register-wavefront DP (1 warp / batch) -----------
__device__ __forceinline__ float lse_cell(int d, int u, float a_u, float a_um1,
                                          float bvv, float lvv) {
    const float NEG = -1e30f;
    int t = d - u;
    if (t < 0 || t > Tn - 1) return NEG;
    float v = (t >= 1) ? (a_u + bvv) : NEG;
    float h = (u >= 1) ? (a_um1 + lvv) : NEG;
    float m = fmaxf(v, h);
    float z = fminf(v, h) - m;
    return m + __logf(1.0f + __expf(z));
}

__global__ __launch_bounds__(32) void dp_kernel(const int* __restrict__ ilen,
                                                const int* __restrict__ llen,
                                                float* __restrict__ out) {
    const float NEG = -1e30f;
    int b = blockIdx.x;
    int lane = threadIdx.x;          // 32
    const float* gb = gd_blank + (size_t)b * ND * 128;
    const float* gl = gd_lab   + (size_t)b * ND * 128;
    int Tl = ilen[b], Ul = llen[b];
    int dfin = Tl - 1 + Ul;
    int u0 = lane * 4;
    bool owner = (u0 <= Ul) && (Ul < u0 + 4);
    float bfin = gb[dfin * 128 + Ul];    // blank_lp[Tl-1, Ul]

    float a0 = (u0 == 0) ? 0.0f : NEG, a1 = NEG, a2 = NEG, a3 = NEG;

    float4 pb[8], pl[8];
#pragma unroll
    for (int s = 0; s < 8; s++) {        // operands for diagonals 1..8 (rows 0..7)
        pb[s] = *(const float4*)&gb[s * 128 + u0];
        pl[s] = *(const float4*)&gl[s * 128 + u0];
    }

    for (int d0 = 1; d0 <= 382; d0 += 8) {
#pragma unroll
        for (int ss = 0; ss < 8; ss++) {
            int d = d0 + ss;
            if (d > 382) break;
            float4 bv = pb[ss], lv = pl[ss];
            int nr = d + 7; if (nr > 381) nr = 381;   // row for diag d+8
            pb[ss] = *(const float4*)&gb[nr * 128 + u0];
            pl[ss] = *(const float4*)&gl[nr * 128 + u0];

            float am1 = __shfl_up_sync(0xffffffffu, a3, 1);   // alpha[u0-1]
            float lm1 = __shfl_up_sync(0xffffffffu, lv.w, 1); // lab[u0-1]

            float n0 = lse_cell(d, u0 + 0, a0, am1, bv.x, lm1);
            float n1 = lse_cell(d, u0 + 1, a1, a0,  bv.y, lv.x);
            float n2 = lse_cell(d, u0 + 2, a2, a1,  bv.z, lv.y);
            float n3 = lse_cell(d, u0 + 3, a3, a2,  bv.w, lv.z);
            a0 = n0; a1 = n1; a2 = n2; a3 = n3;

            if (d == dfin && owner) {
                int j = Ul & 3;
                float av = (j == 0) ? n0 : (j == 1) ? n1 : (j == 2) ? n2 : n3;
                out[b] = -(av + bfin);
            }
        }
    }
}

// ---------------- launcher ---------------------------------------------------
extern "C" void kernel_launch(void* const* d_in, const int* in_sizes, int n_in,
                              void* d_out, int out_size) {
    const float* e      = (const float*)d_in[0];
    const float* p      = (const float*)d_in[1];
    const int*   labels = (const int*)  d_in[2];
    const int*   ilen   = (const int*)  d_in[3];
    const int*   llen   = (const int*)  d_in[4];
    float* out = (float*)d_out;

    cudaFuncSetAttribute(gemm_kernel,
                         cudaFuncAttributeMaxDynamicSharedMemorySize, SMEM_TOT);

    gemm_kernel<<<dim3(4, Bn), 256, SMEM_TOT>>>(e, p, labels);
    dp_kernel<<<Bn, 32>>>(ilen, llen, out);
}

// round 14
// speedup vs baseline: 1.3571x; 1.3571x over previous
#include <cuda_runtime.h>
#include <cuda_bf16.h>
#include <cstdint>

// Problem constants
#define Bn   32
#define Tn   256
#define Un   128
#define Um1  127
#define Vn   4096
#define ND   383            // number of anti-diagonals (Tn+Un-1)

// ---------------- device scratch ---------------------------------------------
__device__ __align__(16) __nv_bfloat16 g_expE[(size_t)Bn * Tn * Vn]; // exp(E) bf16
__device__ __align__(16) __nv_bfloat16 g_expP[(size_t)Bn * Un * Vn]; // exp(P) bf16
__device__ __align__(16) float gd_blank[(size_t)Bn * ND * 128]; // diag-major blank_lp
__device__ __align__(16) float gd_lab  [(size_t)Bn * ND * 128]; // diag-major lab_lp

// ---------------- PTX helpers ------------------------------------------------
__device__ __forceinline__ uint32_t smem_u32(const void* p) {
    uint32_t a;
    asm("{ .reg .u64 t; cvta.to.shared.u64 t, %1; cvt.u32.u64 %0, t; }"
        : "=r"(a) : "l"(p));
    return a;
}
#define CP16(dst, src)   asm volatile("cp.async.cg.shared.global [%0], [%1], 16;" :: "r"(dst), "l"(src) : "memory")
#define CP_COMMIT()      asm volatile("cp.async.commit_group;" ::: "memory")

#define LDSM4(r0, r1, r2, r3, addr) \
    asm volatile("ldmatrix.sync.aligned.m8n8.x4.shared.b16 {%0,%1,%2,%3}, [%4];" \
        : "=r"(r0), "=r"(r1), "=r"(r2), "=r"(r3) : "r"(addr))

#define MMA16816(c, a, bq) \
    asm volatile("mma.sync.aligned.m16n8k16.row.col.f32.bf16.bf16.f32 " \
        "{%0,%1,%2,%3}, {%4,%5,%6,%7}, {%8,%9}, {%0,%1,%2,%3};" \
        : "+f"((c)[0]), "+f"((c)[1]), "+f"((c)[2]), "+f"((c)[3]) \
        : "r"((a)[0]), "r"((a)[1]), "r"((a)[2]), "r"((a)[3]), \
          "r"((bq)[0]), "r"((bq)[1]))

// ---------------- kernel 1: exp + bf16 convert -------------------------------
__global__ void expcvt_kernel(const float* __restrict__ E,
                              const float* __restrict__ P) {
    const size_t NE = (size_t)Bn * Tn * Vn;
    size_t i = ((size_t)blockIdx.x * 256 + threadIdx.x) * 8;
    const float* src;
    __nv_bfloat16* dst;
    if (i < NE) { src = E + i; dst = g_expE + i; }
    else        { src = P + (i - NE); dst = g_expP + (i - NE); }
    float4 v0 = *(const float4*)(src);
    float4 v1 = *(const float4*)(src + 4);
    __nv_bfloat162 o[4];
    o[0] = __floats2bfloat162_rn(__expf(v0.x), __expf(v0.y));
    o[1] = __floats2bfloat162_rn(__expf(v0.z), __expf(v0.w));
    o[2] = __floats2bfloat162_rn(__expf(v1.x), __expf(v1.y));
    o[3] = __floats2bfloat162_rn(__expf(v1.z), __expf(v1.w));
    uint4 pk;
    pk.x = *(uint32_t*)&o[0]; pk.y = *(uint32_t*)&o[1];
    pk.z = *(uint32_t*)&o[2]; pk.w = *(uint32_t*)&o[3];
    *(uint4*)dst = pk;
}

// ---------------- kernel 2: HMMA GEMM, 6-stage pipeline (round-9, best) ------
#define SMEM_HDR  2048
#define STAGE_B   24576
#define NSTAGE    6
#define SMEM_TOT  (SMEM_HDR + NSTAGE * STAGE_B)   // 149504

__global__ __launch_bounds__(256, 1) void gemm_kernel(const float* __restrict__ E,
                                                      const float* __restrict__ P,
                                                      const int* __restrict__ labels) {
    extern __shared__ __align__(1024) char smem[];
    uint32_t sb = smem_u32(smem);
    float* p0s = (float*)(smem);
    float* pls = (float*)(smem + 512);
    int*   lbs = (int*)(smem + 1024);

    int tid = threadIdx.x, lane = tid & 31, wid = tid >> 5;
    int wm = wid >> 2;
    int wn = wid & 3;
    int t0 = blockIdx.x * 64;
    int b  = blockIdx.y;

    if (tid < Un) {
        const float* Pr = P + (size_t)(b * Un + tid) * Vn;
        p0s[tid] = Pr[0];
        if (tid < Um1) {
            int l = labels[b * Um1 + tid];
            lbs[tid] = l;
            pls[tid] = Pr[l];
        }
    }

    auto issue = [&](int k) {
        uint32_t base = sb + SMEM_HDR + (k % NSTAGE) * STAGE_B;
        int r = tid >> 3, c = tid & 7;
        uint32_t sw = (uint32_t)((c ^ (r & 7)) << 4);
        const __nv_bfloat16* asrc = g_expE + (size_t)(b * Tn + t0 + r) * Vn + k * 64 + c * 8;
        CP16(base + r * 128 + sw,        asrc);
        CP16(base + (r + 32) * 128 + sw, asrc + (size_t)32 * Vn);
        const __nv_bfloat16* bsrc = g_expP + (size_t)(b * Un + r) * Vn + k * 64 + c * 8;
        uint32_t bb = base + 8192;
#pragma unroll
        for (int q = 0; q < 4; q++)
            CP16(bb + (r + q * 32) * 128 + sw, bsrc + (size_t)(q * 32) * Vn);
        CP_COMMIT();
    };

    issue(0); issue(1); issue(2); issue(3); issue(4);

    float cr[2][4][4] = {};

    for (int k = 0; k < 64; k++) {
        if      (k <= 59) asm volatile("cp.async.wait_group 4;" ::: "memory");
        else if (k == 60) asm volatile("cp.async.wait_group 3;" ::: "memory");
        else if (k == 61) asm volatile("cp.async.wait_group 2;" ::: "memory");
        else if (k == 62) asm volatile("cp.async.wait_group 1;" ::: "memory");
        else              asm volatile("cp.async.wait_group 0;" ::: "memory");
        __syncthreads();
        if (k + 5 < 64) issue(k + 5);

        uint32_t sA = sb + SMEM_HDR + (k % NSTAGE) * STAGE_B;
        uint32_t sB = sA + 8192;
#pragma unroll
        for (int kf = 0; kf < 4; kf++) {
            uint32_t afr[2][4], bfr[4][2];
#pragma unroll
            for (int mi = 0; mi < 2; mi++) {
                int row = wm * 32 + mi * 16 + (lane & 15);
                int kc  = kf * 2 + (lane >> 4);
                uint32_t ad = sA + row * 128 + (((uint32_t)(kc ^ (row & 7))) << 4);
                LDSM4(afr[mi][0], afr[mi][1], afr[mi][2], afr[mi][3], ad);
            }
#pragma unroll
            for (int p = 0; p < 2; p++) {
                int g = lane >> 3;
                int nrow = wn * 32 + p * 16 + ((g >> 1) << 3) + (lane & 7);
                int kc   = kf * 2 + (g & 1);
                uint32_t bd = sB + nrow * 128 + (((uint32_t)(kc ^ (nrow & 7))) << 4);
                uint32_t r0, r1, r2, r3;
                LDSM4(r0, r1, r2, r3, bd);
                bfr[p * 2 + 0][0] = r0; bfr[p * 2 + 0][1] = r1;
                bfr[p * 2 + 1][0] = r2; bfr[p * 2 + 1][1] = r3;
            }
#pragma unroll
            for (int mi = 0; mi < 2; mi++)
#pragma unroll
                for (int ni = 0; ni < 4; ni++)
                    MMA16816(cr[mi][ni], afr[mi], bfr[ni]);
        }
    }

    float* gbd = gd_blank + (size_t)b * ND * 128;
    float* gld = gd_lab   + (size_t)b * ND * 128;
#pragma unroll
    for (int mi = 0; mi < 2; mi++) {
#pragma unroll
        for (int h = 0; h < 2; h++) {
            int t = t0 + wm * 32 + mi * 16 + h * 8 + (lane >> 2);
            const float* Er = E + (size_t)(b * Tn + t) * Vn;
            float e0 = Er[0];
#pragma unroll
            for (int ni = 0; ni < 4; ni++) {
#pragma unroll
                for (int j = 0; j < 2; j++) {
                    int u = wn * 32 + ni * 8 + (lane & 3) * 2 + j;
                    float ln = __logf(cr[mi][ni][h * 2 + j]);
                    gbd[(t + u) * 128 + u] = e0 + p0s[u] - ln;
                    if (u < Um1)
                        gld[(t + u) * 128 + u] = Er[lbs[u]] + pls[u] - ln;
                }
            }
        }
    }
}

// ---------------- kernel 3: DP with cp.async smem ring -----------------------
// 1 warp per batch. Operand diagonal rows staged into a 16-slot smem ring via
// cp.async, issued 15 rows ahead; consumer does LDS only (prefetched 2 ahead).
// Ring slot s: floats [s*256 .. s*256+127] = blank row, [+128..+255] = lab row.
#define RING 16

__device__ __forceinline__ float lse_cell(int d, int u, float a_u, float a_um1,
                                          float bvv, float lvv) {
    const float NEG = -1e30f;
    int t = d - u;
    if (t < 0 || t > Tn - 1) return NEG;
    float v = (t >= 1) ? (a_u + bvv) : NEG;
    float h = (u >= 1) ? (a_um1 + lvv) : NEG;
    float m = fmaxf(v, h);
    float z = fminf(v, h) - m;
    return m + __logf(1.0f + __expf(z));
}

__global__ __launch_bounds__(32) void dp_kernel(const int* __restrict__ ilen,
                                                const int* __restrict__ llen,
                                                float* __restrict__ out) {
    __shared__ __align__(16) float ring[RING * 256];
    const float NEG = -1e30f;
    int b = blockIdx.x;
    int lane = threadIdx.x;          // 32
    const float* gb = gd_blank + (size_t)b * ND * 128;
    const float* gl = gd_lab   + (size_t)b * ND * 128;
    int Tl = ilen[b], Ul = llen[b];
    int dfin = Tl - 1 + Ul;
    int u0 = lane * 4;
    bool owner = (u0 <= Ul) && (Ul < u0 + 4);
    float bfin = gb[(size_t)dfin * 128 + Ul];   // blank_lp[Tl-1, Ul]

    uint32_t rb32 = smem_u32(ring);
    uint32_t my_off = (uint32_t)(lane * 16);    // per-thread 16B within half-slot

    // issue cp.async for operand row r into slot r%RING (1 group per row)
#define DP_ISSUE(rr_) do {                                            \
        int _r = (rr_); int _rc = _r <= 381 ? _r : 381;               \
        uint32_t _dst = rb32 + (uint32_t)((_r & (RING - 1)) * 1024) + my_off; \
        CP16(_dst,       gb + (size_t)_rc * 128 + u0);                \
        CP16(_dst + 512, gl + (size_t)_rc * 128 + u0);                \
        CP_COMMIT();                                                  \
    } while (0)

#pragma unroll
    for (int r = 0; r < 15; r++) DP_ISSUE(r);      // rows 0..14 in flight
    asm volatile("cp.async.wait_group 13;" ::: "memory");  // rows 0,1 done

    // register prefetch rows 0 (cur) and 1 (nxt)
    float4 bvc = *(float4*)&ring[0 * 256 + lane * 4];
    float4 lvc = *(float4*)&ring[0 * 256 + 128 + lane * 4];
    float4 bvn = *(float4*)&ring[1 * 256 + lane * 4];
    float4 lvn = *(float4*)&ring[1 * 256 + 128 + lane * 4];

    float a0 = (u0 == 0) ? 0.0f : NEG, a1 = NEG, a2 = NEG, a3 = NEG;

    for (int r = 0; r < 382; r++) {
        int d = r + 1;                    // diagonal; operand row = r

        float am1 = __shfl_up_sync(0xffffffffu, a3, 1);     // alpha[u0-1]
        float lm1 = __shfl_up_sync(0xffffffffu, lvc.w, 1);  // lab[u0-1]

        float n0 = lse_cell(d, u0 + 0, a0, am1, bvc.x, lm1);
        float n1 = lse_cell(d, u0 + 1, a1, a0,  bvc.y, lvc.x);
        float n2 = lse_cell(d, u0 + 2, a2, a1,  bvc.z, lvc.y);
        float n3 = lse_cell(d, u0 + 3, a3, a2,  bvc.w, lvc.z);
        a0 = n0; a1 = n1; a2 = n2; a3 = n3;

        if (d == dfin && owner) {
            int j = Ul & 3;
            float av = (j == 0) ? n0 : (j == 1) ? n1 : (j == 2) ? n2 : n3;
            out[b] = -(av + bfin);
        }

        // keep the ring primed: issue row r+15, ensure row r+2 resident, LDS it
        DP_ISSUE(r + 15);
        asm volatile("cp.async.wait_group 13;" ::: "memory");
        int s2 = (r + 2) & (RING - 1);
        float4 bvf = *(float4*)&ring[s2 * 256 + lane * 4];
        float4 lvf = *(float4*)&ring[s2 * 256 + 128 + lane * 4];
        bvc = bvn; lvc = lvn;
        bvn = bvf; lvn = lvf;
    }
#undef DP_ISSUE
}

// ---------------- launcher ---------------------------------------------------
extern "C" void kernel_launch(void* const* d_in, const int* in_sizes, int n_in,
                              void* d_out, int out_size) {
    const float* e      = (const float*)d_in[0];
    const float* p      = (const float*)d_in[1];
    const int*   labels = (const int*)  d_in[2];
    const int*   ilen   = (const int*)  d_in[3];
    const int*   llen   = (const int*)  d_in[4];
    float* out = (float*)d_out;

    cudaFuncSetAttribute(gemm_kernel,
                         cudaFuncAttributeMaxDynamicSharedMemorySize, SMEM_TOT);

    expcvt_kernel<<<24576, 256>>>(e, p);
    gemm_kernel<<<dim3(4, Bn), 256, SMEM_TOT>>>(e, p, labels);
    dp_kernel<<<Bn, 32>>>(ilen, llen, out);
}